// round 10
// baseline (speedup 1.0000x reference)
#include <cuda_runtime.h>
#include <cstddef>

// Ghost-cell padding with affine boundary conditions.
// arr: (4, 4096, 4096) f32 -> out: (4, 4098, 4098) f32
//
// Round-10 change vs round-6 (single variable): block size 512 -> 256.
// Identical burst structure (2 rows staged in 32 KB smem: read burst ->
// one barrier -> write burst), but 7 CTAs/SM instead of 4: more independent
// burst streams per SM so reads of some CTAs overlap writes of others,
// smaller/cheaper barrier groups, double per-thread work.

static constexpr int F  = 4;
static constexpr int NX = 4096;
static constexpr int NY = 4096;
static constexpr int PX = NX + 2;   // 4098
static constexpr int PY = NY + 2;   // 4098

static constexpr int THREADS = 256;
static constexpr int RPB     = 2;   // padded rows per block; 4098 = 2 * 2049

__global__ void __launch_bounds__(THREADS)
ghost_pad_kernel(const float* __restrict__ arr,
                 const float* __restrict__ bc,   // bc_const  flat [axis*2+side]
                 const float* __restrict__ bf,   // bc_factor flat [axis*2+side]
                 float* __restrict__ out)
{
    __shared__ float s[RPB][NY];    // staged input rows (32 KB)

    const int row0 = blockIdx.x * RPB;   // first padded row of this block
    const int f    = blockIdx.y;         // field
    const int t    = threadIdx.x;

    // Phase 1: stage RPB source rows into smem, aligned 16B streaming loads.
    // Per row: 1024 float4, 256 threads -> 4 iterations.
    #pragma unroll
    for (int rr = 0; rr < RPB; rr++) {
        const int row = row0 + rr;
        const int src = (row == 0) ? 0 : ((row == PX - 1) ? (NX - 1) : (row - 1));
        const float* __restrict__ a = arr + ((size_t)f * NX + src) * NY;
        #pragma unroll
        for (int i = 0; i < 4; i++) {
            const int k = 4 * (t + i * THREADS);          // 0..4092, mult of 4
            *reinterpret_cast<float4*>(&s[rr][k]) =
                __ldcs(reinterpret_cast<const float4*>(a + k));
        }
    }
    __syncthreads();

    // Phase 2: per row, shifted smem reads + coalesced 8B streaming stores.
    // Pairs (j, j+1), j = 2*(t + i*256): 8 iterations cover output 0..4095.
    #pragma unroll
    for (int rr = 0; rr < RPB; rr++) {
        const int row = row0 + rr;

        float fac, c, edgeL, edgeR;
        if (row == 0) {
            c = bc[0]; fac = bf[0];                       // top ghost row
            edgeL = 0.0f; edgeR = 0.0f;
        } else if (row == PX - 1) {
            c = bc[1]; fac = bf[1];                       // bottom ghost row
            edgeL = 0.0f; edgeR = 0.0f;
        } else {
            c = 0.0f; fac = 1.0f;                         // fma(1,x,0) == x
            edgeL = fmaf(bf[2], s[rr][0],      bc[2]);
            edgeR = fmaf(bf[3], s[rr][NY - 1], bc[3]);
        }

        // Row base offset = (f*PX + row) * 4098 -> always even,
        // so float2 stores at even j are 8B-aligned.
        float* __restrict__ orow = out + ((size_t)f * PX + row) * PY;

        #pragma unroll
        for (int i = 0; i < 8; i++) {
            const int j = 2 * (t + i * THREADS);          // 0..4094, even
            const float l0 = s[rr][(j == 0) ? 0 : (j - 1)];
            const float l1 = s[rr][j];
            float v0 = fmaf(fac, l0, c);
            if (j == 0) v0 = edgeL;                       // single thread
            const float v1 = fmaf(fac, l1, c);
            __stcs(reinterpret_cast<float2*>(orow + j), make_float2(v0, v1));
        }

        // Tail pair: positions 4096 (from a[4095]) and 4097 (right edge).
        if (t == 0) {
            __stcs(reinterpret_cast<float2*>(orow + (PY - 2)),
                   make_float2(fmaf(fac, s[rr][NY - 1], c), edgeR));
        }
    }
}

extern "C" void kernel_launch(void* const* d_in, const int* in_sizes, int n_in,
                              void* d_out, int out_size)
{
    const float* arr       = (const float*)d_in[0];
    const float* bc_const  = (const float*)d_in[1];
    const float* bc_factor = (const float*)d_in[2];
    float* out             = (float*)d_out;

    dim3 grid(PX / RPB, F);         // 2049 x 4
    ghost_pad_kernel<<<grid, THREADS>>>(arr, bc_const, bc_factor, out);
}

// round 11
// speedup vs baseline: 1.1730x; 1.1730x over previous
#include <cuda_runtime.h>
#include <cstddef>

// Ghost-cell padding with affine boundary conditions — FINAL (round-6 config).
// arr: (4, 4096, 4096) f32 -> out: (4, 4098, 4098) f32
//
// Best configuration found over 10 rounds of search:
//   - 2 padded rows per CTA staged in 32 KB smem: 32 KB aligned-LDG.128 read
//     burst -> one barrier -> 32 KB 8B-aligned STG.64 write burst. The burst
//     coarsening is what lifted DRAM from 73% -> 79% of spec (bus-turnaround
//     reduction); RPB=1/3, persistent CTAs, register staging, shfl realign,
//     and 256/1024-thread blocks all regressed.
//   - 512 threads x 4 CTAs/SM = full 2048 threads/SM (max MLP).
//   - Streaming cache hints (touch-once 537 MB footprint vs 126 MB L2).
//   - Unified row model: orow[p] = fma(fac, a[p-1], c) with (fac,c)=(1,0)
//     for interior copy rows (exact), bc[axis0,side] for top/bottom ghost
//     rows; edges/corners overridden at j==0 and j==PY-1.
// Achieves ~7.0 TB/s combined r+w (79.3% of 8 TB/s HBM spec).

static constexpr int F  = 4;
static constexpr int NX = 4096;
static constexpr int NY = 4096;
static constexpr int PX = NX + 2;   // 4098
static constexpr int PY = NY + 2;   // 4098

static constexpr int THREADS = 512;
static constexpr int RPB     = 2;   // padded rows per block; 4098 = 2 * 2049

__global__ void __launch_bounds__(THREADS)
ghost_pad_kernel(const float* __restrict__ arr,
                 const float* __restrict__ bc,   // bc_const  flat [axis*2+side]
                 const float* __restrict__ bf,   // bc_factor flat [axis*2+side]
                 float* __restrict__ out)
{
    __shared__ float s[RPB][NY];    // staged input rows (32 KB)

    const int row0 = blockIdx.x * RPB;   // first padded row of this block
    const int f    = blockIdx.y;         // field
    const int t    = threadIdx.x;

    // Phase 1: stage RPB source rows into smem, aligned 16B streaming loads.
    #pragma unroll
    for (int rr = 0; rr < RPB; rr++) {
        const int row = row0 + rr;
        const int src = (row == 0) ? 0 : ((row == PX - 1) ? (NX - 1) : (row - 1));
        const float* __restrict__ a = arr + ((size_t)f * NX + src) * NY;
        #pragma unroll
        for (int i = 0; i < 2; i++) {
            const int k = 4 * (t + i * THREADS);          // 0..4092, mult of 4
            *reinterpret_cast<float4*>(&s[rr][k]) =
                __ldcs(reinterpret_cast<const float4*>(a + k));
        }
    }
    __syncthreads();

    // Phase 2: per row, shifted read from smem + coalesced 8B streaming stores.
    #pragma unroll
    for (int rr = 0; rr < RPB; rr++) {
        const int row = row0 + rr;

        float fac, c, edgeL, edgeR;
        if (row == 0) {
            c = bc[0]; fac = bf[0];                       // top ghost row
            edgeL = 0.0f; edgeR = 0.0f;
        } else if (row == PX - 1) {
            c = bc[1]; fac = bf[1];                       // bottom ghost row
            edgeL = 0.0f; edgeR = 0.0f;
        } else {
            c = 0.0f; fac = 1.0f;                         // fma(1,x,0) == x
            edgeL = fmaf(bf[2], s[rr][0],      bc[2]);
            edgeR = fmaf(bf[3], s[rr][NY - 1], bc[3]);
        }

        // Row base offset = (f*PX + row) * 4098 -> always even,
        // so float2 stores at even j are 8B-aligned.
        float* __restrict__ orow = out + ((size_t)f * PX + row) * PY;

        #pragma unroll
        for (int i = 0; i < 4; i++) {
            const int j = 2 * (t + i * THREADS);          // 0..4094, even
            const float l0 = s[rr][(j == 0) ? 0 : (j - 1)];
            const float l1 = s[rr][j];
            float v0 = fmaf(fac, l0, c);
            if (j == 0) v0 = edgeL;                       // single thread
            const float v1 = fmaf(fac, l1, c);
            __stcs(reinterpret_cast<float2*>(orow + j), make_float2(v0, v1));
        }

        // Tail pair: positions 4096 (from a[4095]) and 4097 (right edge).
        if (t == 0) {
            __stcs(reinterpret_cast<float2*>(orow + (PY - 2)),
                   make_float2(fmaf(fac, s[rr][NY - 1], c), edgeR));
        }
    }
}

extern "C" void kernel_launch(void* const* d_in, const int* in_sizes, int n_in,
                              void* d_out, int out_size)
{
    const float* arr       = (const float*)d_in[0];
    const float* bc_const  = (const float*)d_in[1];
    const float* bc_factor = (const float*)d_in[2];
    float* out             = (float*)d_out;

    dim3 grid(PX / RPB, F);         // 2049 x 4
    ghost_pad_kernel<<<grid, THREADS>>>(arr, bc_const, bc_factor, out);
}